// round 14
// baseline (speedup 1.0000x reference)
#include <cuda_runtime.h>
#include <math.h>

#define DIM 512
#define MARGIN 1.0f
#define RULE_WEIGHT 0.5f

#define MAX_B   1024
#define MAX_NEG 8192

// Scratch (allocation-free). Accumulate-only globals; reset by ticketed last
// block each call so graph replays are deterministic.
__device__ float g_loss = 0.f;
__device__ float g_rule_sum = 0.f;
__device__ unsigned int g_ticket = 0;
// Fallback-path scratch (generic ratio):
__device__ float g_dposm[MAX_B];
__device__ float g_dneg[MAX_NEG];

__device__ __forceinline__ float warp_red(float v) {
#pragma unroll
    for (int o = 16; o; o >>= 1) v += __shfl_xor_sync(0xffffffffu, v, o);
    return v;
}

// acq_rel ticket (validated R10/R13): release orders this thread's prior
// global atomics before the increment; winner's acquire orders later reads.
__device__ __forceinline__ unsigned int ticket_acq_rel(unsigned int* p) {
    unsigned int old;
    asm volatile("atom.acq_rel.gpu.global.add.u32 %0, [%1], 1;"
                 : "=r"(old) : "l"(p) : "memory");
    return old;
}

// TransH distance via expanded norm (R11, measured win): single streaming
// pass over w and re; only hd[4] + 4 scalar accumulators live.
//   u = hd + re;  ||u - c*w||^2 = uu - 2c*uw + c^2*ww,  c = (hd.w)/ww
__device__ __forceinline__ float dist_lowreg(
    const float4 hd[4],
    const float* __restrict__ rel, const float* __restrict__ nv,
    int r, int lane)
{
    const float4* w4  = reinterpret_cast<const float4*>(nv  + (size_t)r * DIM);
    const float4* re4 = reinterpret_cast<const float4*>(rel + (size_t)r * DIM);
    float ww = 0.f, dw = 0.f, uu = 0.f, uw = 0.f;
#pragma unroll
    for (int i = 0; i < 4; i++) {
        float4 w  = w4[lane + 32 * i];
        float4 re = re4[lane + 32 * i];
        float ux = hd[i].x + re.x, uy = hd[i].y + re.y;
        float uz = hd[i].z + re.z, uq = hd[i].w + re.w;
        ww += w.x * w.x + w.y * w.y + w.z * w.z + w.w * w.w;
        dw += hd[i].x * w.x + hd[i].y * w.y + hd[i].z * w.z + hd[i].w * w.w;
        uu += ux * ux + uy * uy + uz * uz + uq * uq;
        uw += ux * w.x + uy * w.y + uz * w.z + uq * w.w;
    }
    ww = warp_red(ww);
    dw = warp_red(dw);
    uu = warp_red(uu);
    uw = warp_red(uw);
    float c = dw / ww;
    float ss = uu - 2.f * c * uw + c * c * ww;
    return sqrtf(fmaxf(ss, 0.f));
}

__device__ __forceinline__ void load_hd(
    float4 hd[4], const float* __restrict__ ent, int h, int t, int lane)
{
    const float4* he4 = reinterpret_cast<const float4*>(ent + (size_t)h * DIM);
    const float4* te4 = reinterpret_cast<const float4*>(ent + (size_t)t * DIM);
#pragma unroll
    for (int i = 0; i < 4; i++) {
        float4 a = he4[lane + 32 * i];
        float4 b = te4[lane + 32 * i];
        hd[i].x = a.x - b.x; hd[i].y = a.y - b.y;
        hd[i].z = a.z - b.z; hd[i].w = a.w - b.w;
    }
}

// ratio==8 path: one block = 1 pos warp (wid 8) + 8 neg warps. Pairing is
// PURELY intra-block (smem). Rules run AFTER the publish barrier so neg
// warps never wait on them (fixes R2's coupling). Globals are accumulate-
// only; ticketed last block writes out and resets.
__global__ void __launch_bounds__(288)
fused9(const int* __restrict__ pos, const int* __restrict__ neg,
       const int* __restrict__ rr1, const int* __restrict__ rr2,
       const float* __restrict__ rconf,
       const float* __restrict__ ent, const float* __restrict__ rel,
       const float* __restrict__ nv,
       float* __restrict__ out,
       int B, int NEG, int NR)
{
    int tid  = threadIdx.x;
    int wid  = tid >> 5;
    int lane = tid & 31;
    int b    = blockIdx.x;
    int ratio = NEG / B;                 // 8 on this path

    __shared__ float s_pm;               // MARGIN + d_pos
    __shared__ float s_loss;
    if (tid == 0) s_loss = 0.f;

    bool is_pos = (wid == ratio);
    int h, r, t;
    if (is_pos) {
        h = pos[3 * b]; r = pos[3 * b + 1]; t = pos[3 * b + 2];
    } else {
        int k = b * ratio + wid;
        h = neg[3 * k]; r = neg[3 * k + 1]; t = neg[3 * k + 2];
    }

    float4 hd[4];
    load_hd(hd, ent, h, t, lane);
    float d = dist_lowreg(hd, rel, nv, r, lane);

    if (is_pos && lane == 0) s_pm = MARGIN + d;
    __syncthreads();                      // publish d_pos (and s_loss init)

    if (!is_pos) {
        float v = s_pm - d;               // MARGIN + d_pos - d_neg
        if (lane == 0 && v > 0.f) atomicAdd(&s_loss, v);
    } else {
        // Rules AFTER the barrier: overlaps the neg warps' pairing; only
        // rules with rule_r1[j] == r contribute (mask exact-zeros the rest).
        float racc = 0.f;
        for (int j = 0; j < NR; j++) {
            if (rr1[j] == r)
                racc += rconf[j] * dist_lowreg(hd, rel, nv, rr2[j], lane);
        }
        if (lane == 0 && racc != 0.f) atomicAdd(&g_rule_sum, racc);
    }
    __syncthreads();

    __shared__ unsigned int s_last;
    if (tid == 0) {
        if (s_loss != 0.f) atomicAdd(&g_loss, s_loss);
        s_last = (ticket_acq_rel(&g_ticket) == gridDim.x - 1) ? 1u : 0u;
    }
    __syncthreads();
    if (!s_last) return;

    if (tid == 0) {
        out[0] = __ldcg(&g_loss) / (float)NEG + RULE_WEIGHT * __ldcg(&g_rule_sum);
        g_loss = 0.f;
        g_rule_sum = 0.f;
        g_ticket = 0;
    }
}

// ---------- Fallback path (generic ratio): proven R11 two-kernel pipeline ----------
__global__ void __launch_bounds__(256)
dist_kernel(const int* __restrict__ pos, const int* __restrict__ neg,
            const int* __restrict__ rr1, const int* __restrict__ rr2,
            const float* __restrict__ rconf,
            const float* __restrict__ ent, const float* __restrict__ rel,
            const float* __restrict__ nv,
            float* __restrict__ out,
            int B, int NEG, int NR)
{
    if (blockIdx.x == 0 && threadIdx.x == 0) out[0] = 0.f;
    int gw   = (blockIdx.x * blockDim.x + threadIdx.x) >> 5;
    int lane = threadIdx.x & 31;
    if (gw >= B + NEG) return;

    int h, r, t;
    bool is_pos = (gw < B);
    if (is_pos) { h = pos[3 * gw]; r = pos[3 * gw + 1]; t = pos[3 * gw + 2]; }
    else { int k = gw - B; h = neg[3 * k]; r = neg[3 * k + 1]; t = neg[3 * k + 2]; }

    float4 hd[4];
    load_hd(hd, ent, h, t, lane);
    float d = dist_lowreg(hd, rel, nv, r, lane);

    if (is_pos) {
        float racc = 0.f;
        for (int j = 0; j < NR; j++)
            if (rr1[j] == r) racc += rconf[j] * dist_lowreg(hd, rel, nv, rr2[j], lane);
        if (lane == 0) {
            g_dposm[gw] = MARGIN + d;
            if (racc != 0.f) atomicAdd(&g_rule_sum, racc);
        }
    } else if (lane == 0) g_dneg[gw - B] = d;
}

__global__ void __launch_bounds__(256)
final_reduce(float* __restrict__ out, int B, int NEG)
{
    __shared__ float sb[256];
    int tid = threadIdx.x;
    int gt  = blockIdx.x * blockDim.x + tid;
    int ratio = NEG / B;
    float acc = 0.f;
    for (int k = gt; k < NEG; k += gridDim.x * blockDim.x) {
        float v = g_dposm[k / ratio] - g_dneg[k];
        acc += (v > 0.f) ? v : 0.f;
    }
    sb[tid] = acc;
    __syncthreads();
    for (int s = 128; s; s >>= 1) { if (tid < s) sb[tid] += sb[tid + s]; __syncthreads(); }
    if (tid == 0) {
        float contrib = sb[0] / (float)NEG;
        if (blockIdx.x == 0) { contrib += RULE_WEIGHT * g_rule_sum; g_rule_sum = 0.f; }
        atomicAdd(out, contrib);
    }
}

extern "C" void kernel_launch(void* const* d_in, const int* in_sizes, int n_in,
                              void* d_out, int out_size)
{
    const int*   pos   = (const int*)d_in[0];
    const int*   neg   = (const int*)d_in[1];
    const int*   rr1   = (const int*)d_in[2];
    const int*   rr2   = (const int*)d_in[3];
    const float* rconf = (const float*)d_in[4];
    const float* ent   = (const float*)d_in[5];
    const float* rel   = (const float*)d_in[6];
    const float* nv    = (const float*)d_in[7];

    int B   = in_sizes[0] / 3;
    int NEG = in_sizes[1] / 3;
    int NR  = in_sizes[2];
    int ratio = NEG / B;

    if (ratio == 8 && NEG == B * 8) {
        fused9<<<B, 288>>>(pos, neg, rr1, rr2, rconf, ent, rel, nv,
                           (float*)d_out, B, NEG, NR);
    } else {
        int totalWarps = B + NEG;
        int blocks = (totalWarps * 32 + 255) / 256;
        dist_kernel<<<blocks, 256>>>(pos, neg, rr1, rr2, rconf, ent, rel, nv,
                                     (float*)d_out, B, NEG, NR);
        int rblocks = ((NEG >> 2) + 255) / 256;
        if (rblocks < 1) rblocks = 1;
        final_reduce<<<rblocks, 256>>>((float*)d_out, B, NEG);
    }
}

// round 15
// speedup vs baseline: 1.0019x; 1.0019x over previous
#include <cuda_runtime.h>
#include <math.h>

#define DIM 512
#define MARGIN 1.0f
#define RULE_WEIGHT 0.5f

#define MAX_NEG 8192

// Scratch (allocation-free). Accumulate-only; ticketed last block of node 2
// writes out[0] and resets, so graph replays are deterministic.
__device__ float g_dneg[MAX_NEG];
__device__ float g_loss = 0.f;
__device__ unsigned int g_ticket = 0;

__device__ __forceinline__ float warp_red(float v) {
#pragma unroll
    for (int o = 16; o; o >>= 1) v += __shfl_xor_sync(0xffffffffu, v, o);
    return v;
}

// acq_rel ticket (validated R10/R14): release orders this thread's prior
// global atomics before the increment; winner's acquire orders later reads.
__device__ __forceinline__ unsigned int ticket_acq_rel(unsigned int* p) {
    unsigned int old;
    asm volatile("atom.acq_rel.gpu.global.add.u32 %0, [%1], 1;"
                 : "=r"(old) : "l"(p) : "memory");
    return old;
}

// TransH distance via expanded norm (R11, measured win): single streaming
// pass over w and re; only hd[4] + 4 scalar accumulators live.
//   u = hd + re;  ||u - c*w||^2 = uu - 2c*uw + c^2*ww,  c = (hd.w)/ww
__device__ __forceinline__ float dist_lowreg(
    const float4 hd[4],
    const float* __restrict__ rel, const float* __restrict__ nv,
    int r, int lane)
{
    const float4* w4  = reinterpret_cast<const float4*>(nv  + (size_t)r * DIM);
    const float4* re4 = reinterpret_cast<const float4*>(rel + (size_t)r * DIM);
    float ww = 0.f, dw = 0.f, uu = 0.f, uw = 0.f;
#pragma unroll
    for (int i = 0; i < 4; i++) {
        float4 w  = w4[lane + 32 * i];
        float4 re = re4[lane + 32 * i];
        float ux = hd[i].x + re.x, uy = hd[i].y + re.y;
        float uz = hd[i].z + re.z, uq = hd[i].w + re.w;
        ww += w.x * w.x + w.y * w.y + w.z * w.z + w.w * w.w;
        dw += hd[i].x * w.x + hd[i].y * w.y + hd[i].z * w.z + hd[i].w * w.w;
        uu += ux * ux + uy * uy + uz * uz + uq * uq;
        uw += ux * w.x + uy * w.y + uz * w.z + uq * w.w;
    }
    ww = warp_red(ww);
    dw = warp_red(dw);
    uu = warp_red(uu);
    uw = warp_red(uw);
    float c = dw / ww;
    float ss = uu - 2.f * c * uw + c * c * ww;
    return sqrtf(fmaxf(ss, 0.f));
}

__device__ __forceinline__ void load_hd(
    float4 hd[4], const float* __restrict__ ent, int h, int t, int lane)
{
    const float4* he4 = reinterpret_cast<const float4*>(ent + (size_t)h * DIM);
    const float4* te4 = reinterpret_cast<const float4*>(ent + (size_t)t * DIM);
#pragma unroll
    for (int i = 0; i < 4; i++) {
        float4 a = he4[lane + 32 * i];
        float4 b = te4[lane + 32 * i];
        hd[i].x = a.x - b.x; hd[i].y = a.y - b.y;
        hd[i].z = a.z - b.z; hd[i].w = a.w - b.w;
    }
}

// ---- Node 1: negs only. One warp per neg distance; fully independent. ----
__global__ void __launch_bounds__(256)
neg_kernel(const int* __restrict__ neg,
           const float* __restrict__ ent, const float* __restrict__ rel,
           const float* __restrict__ nv,
           int NEG)
{
    int gw   = (blockIdx.x * blockDim.x + threadIdx.x) >> 5;
    int lane = threadIdx.x & 31;
    if (gw >= NEG) return;

    int h = neg[3 * gw], r = neg[3 * gw + 1], t = neg[3 * gw + 2];
    float4 hd[4];
    load_hd(hd, ent, h, t, lane);
    float d = dist_lowreg(hd, rel, nv, r, lane);
    if (lane == 0) g_dneg[gw] = d;
}

// ---- Node 2: pos + rules + pairing + scalar finish. One warp per pos
// triple. Kernel boundary makes g_dneg visible — NO handoff machinery.
// Each warp reads its own `ratio` neg dists (contiguous, L2-hot), folds the
// relu sum and its rule terms into one contrib, accumulated via smem + one
// REDG per block. Acq_rel-ticketed last block writes out[0] and resets. ----
__global__ void __launch_bounds__(128)
pos_pair_kernel(const int* __restrict__ pos,
                const int* __restrict__ rr1, const int* __restrict__ rr2,
                const float* __restrict__ rconf,
                const float* __restrict__ ent, const float* __restrict__ rel,
                const float* __restrict__ nv,
                float* __restrict__ out,
                int B, int NEG, int NR)
{
    int tid  = threadIdx.x;
    int gw   = (blockIdx.x * blockDim.x + tid) >> 5;
    int lane = tid & 31;
    int ratio = NEG / B;

    __shared__ float s_loss;
    if (tid == 0) s_loss = 0.f;
    __syncthreads();

    if (gw < B) {
        int h = pos[3 * gw], r = pos[3 * gw + 1], t = pos[3 * gw + 2];
        float4 hd[4];
        load_hd(hd, ent, h, t, lane);
        float d = dist_lowreg(hd, rel, nv, r, lane);
        float pm = MARGIN + d;

        // Pairing: lanes < ratio each read one of this triple's neg dists.
        float v = 0.f;
        for (int k = lane; k < ratio; k += 32) {
            float dn = g_dneg[gw * ratio + k];
            float x = pm - dn;
            v += (x > 0.f) ? x : 0.f;
        }
        v = warp_red(v);

        // Rules: only rule_r1[j] == r contributes (mask exact-zeros the rest).
        float racc = 0.f;
        for (int j = 0; j < NR; j++) {
            if (rr1[j] == r)
                racc += rconf[j] * dist_lowreg(hd, rel, nv, rr2[j], lane);
        }

        if (lane == 0) {
            float contrib = v / (float)NEG + RULE_WEIGHT * racc;
            atomicAdd(&s_loss, contrib);
        }
    }

    __syncthreads();
    __shared__ unsigned int s_last;
    if (tid == 0) {
        if (s_loss != 0.f) atomicAdd(&g_loss, s_loss);
        s_last = (ticket_acq_rel(&g_ticket) == gridDim.x - 1) ? 1u : 0u;
    }
    __syncthreads();
    if (!s_last) return;

    if (tid == 0) {
        out[0] = __ldcg(&g_loss);
        g_loss = 0.f;            // reset for next graph replay (deterministic)
        g_ticket = 0;
    }
}

extern "C" void kernel_launch(void* const* d_in, const int* in_sizes, int n_in,
                              void* d_out, int out_size)
{
    const int*   pos   = (const int*)d_in[0];
    const int*   neg   = (const int*)d_in[1];
    const int*   rr1   = (const int*)d_in[2];
    const int*   rr2   = (const int*)d_in[3];
    const float* rconf = (const float*)d_in[4];
    const float* ent   = (const float*)d_in[5];
    const float* rel   = (const float*)d_in[6];
    const float* nv    = (const float*)d_in[7];

    int B   = in_sizes[0] / 3;
    int NEG = in_sizes[1] / 3;
    int NR  = in_sizes[2];

    // Node 1: 8192 neg warps.
    int nblocks = (NEG * 32 + 255) / 256;
    neg_kernel<<<nblocks, 256>>>(neg, ent, rel, nv, NEG);

    // Node 2: 1024 pos warps, 4 warps/block -> 256 blocks (spread wide).
    int pblocks = (B * 32 + 127) / 128;
    pos_pair_kernel<<<pblocks, 128>>>(pos, rr1, rr2, rconf, ent, rel, nv,
                                      (float*)d_out, B, NEG, NR);
}

// round 16
// speedup vs baseline: 1.0152x; 1.0133x over previous
#include <cuda_runtime.h>
#include <math.h>

#define DIM 512
#define MARGIN 1.0f
#define RULE_WEIGHT 0.5f

// Accumulate-only globals; ticketed last block writes out[0] and resets,
// so graph replays are deterministic.
__device__ float g_loss = 0.f;
__device__ unsigned int g_ticket = 0;

__device__ __forceinline__ float warp_red(float v) {
#pragma unroll
    for (int o = 16; o; o >>= 1) v += __shfl_xor_sync(0xffffffffu, v, o);
    return v;
}

// acq_rel ticket (validated R10/R14): release orders this thread's prior
// global atomics before the increment; winner's acquire orders later reads.
__device__ __forceinline__ unsigned int ticket_acq_rel(unsigned int* p) {
    unsigned int old;
    asm volatile("atom.acq_rel.gpu.global.add.u32 %0, [%1], 1;"
                 : "=r"(old) : "l"(p) : "memory");
    return old;
}

// TransH distance via expanded norm (R11, measured win): single streaming
// pass over w and re; only hd[4] + 4 scalar accumulators live.
//   u = hd + re;  ||u - c*w||^2 = uu - 2c*uw + c^2*ww,  c = (hd.w)/ww
__device__ __forceinline__ float dist_lowreg(
    const float4 hd[4],
    const float* __restrict__ rel, const float* __restrict__ nv,
    int r, int lane)
{
    const float4* w4  = reinterpret_cast<const float4*>(nv  + (size_t)r * DIM);
    const float4* re4 = reinterpret_cast<const float4*>(rel + (size_t)r * DIM);
    float ww = 0.f, dw = 0.f, uu = 0.f, uw = 0.f;
#pragma unroll
    for (int i = 0; i < 4; i++) {
        float4 w  = w4[lane + 32 * i];
        float4 re = re4[lane + 32 * i];
        float ux = hd[i].x + re.x, uy = hd[i].y + re.y;
        float uz = hd[i].z + re.z, uq = hd[i].w + re.w;
        ww += w.x * w.x + w.y * w.y + w.z * w.z + w.w * w.w;
        dw += hd[i].x * w.x + hd[i].y * w.y + hd[i].z * w.z + hd[i].w * w.w;
        uu += ux * ux + uy * uy + uz * uz + uq * uq;
        uw += ux * w.x + uy * w.y + uz * w.z + uq * w.w;
    }
    ww = warp_red(ww);
    dw = warp_red(dw);
    uu = warp_red(uu);
    uw = warp_red(uw);
    float c = dw / ww;
    float ss = uu - 2.f * c * uw + c * c * ww;
    return sqrtf(fmaxf(ss, 0.f));
}

__device__ __forceinline__ void load_hd(
    float4 hd[4], const float* __restrict__ ent, int h, int t, int lane)
{
    const float4* he4 = reinterpret_cast<const float4*>(ent + (size_t)h * DIM);
    const float4* te4 = reinterpret_cast<const float4*>(ent + (size_t)t * DIM);
#pragma unroll
    for (int i = 0; i < 4; i++) {
        float4 a = he4[lane + 32 * i];
        float4 b = te4[lane + 32 * i];
        hd[i].x = a.x - b.x; hd[i].y = a.y - b.y;
        hd[i].z = a.z - b.z; hd[i].w = a.w - b.w;
    }
}

// Task-sequential warps: ONE warp owns pos triple gw, its rule terms, and
// its `ratio` neg triples. Pairing is intra-warp — no second kernel, no
// block barriers between warps, no cross-block handoff. Warps are fully
// independent; only a trivial ticketed scalar tail remains.
__global__ void __launch_bounds__(256)
all_in_warp(const int* __restrict__ pos, const int* __restrict__ neg,
            const int* __restrict__ rr1, const int* __restrict__ rr2,
            const float* __restrict__ rconf,
            const float* __restrict__ ent, const float* __restrict__ rel,
            const float* __restrict__ nv,
            float* __restrict__ out,
            int B, int NEG, int NR)
{
    int tid  = threadIdx.x;
    int gw   = (blockIdx.x * blockDim.x + tid) >> 5;
    int lane = tid & 31;
    int ratio = NEG / B;

    if (gw < B) {
        // ---- pos distance ----
        int h = pos[3 * gw], r = pos[3 * gw + 1], t = pos[3 * gw + 2];
        float4 hd[4];
        load_hd(hd, ent, h, t, lane);
        float pm = MARGIN + dist_lowreg(hd, rel, nv, r, lane);

        // ---- rule terms (reuse pos hd while live); mask exact-zeros rest ----
        float racc = 0.f;
        for (int j = 0; j < NR; j++) {
            if (rr1[j] == r)
                racc += rconf[j] * dist_lowreg(hd, rel, nv, rr2[j], lane);
        }

        // ---- this triple's negs: sequential, hd registers reused ----
        float acc = 0.f;
        for (int j = 0; j < ratio; j++) {
            int k = gw * ratio + j;
            int h2 = neg[3 * k], r2 = neg[3 * k + 1], t2 = neg[3 * k + 2];
            load_hd(hd, ent, h2, t2, lane);
            float dn = dist_lowreg(hd, rel, nv, r2, lane);
            float x = pm - dn;                  // MARGIN + d_pos - d_neg
            acc += (x > 0.f) ? x : 0.f;
        }

        if (lane == 0) {
            float contrib = acc / (float)NEG + RULE_WEIGHT * racc;
            atomicAdd(&g_loss, contrib);        // 1024 REDG-class atomics total
        }
    }

    // ---- trivial ticketed tail ----
    __syncthreads();                            // all warps' atomics issued
    __shared__ unsigned int s_last;
    if (tid == 0)
        s_last = (ticket_acq_rel(&g_ticket) == gridDim.x - 1) ? 1u : 0u;
    __syncthreads();
    if (!s_last) return;

    if (tid == 0) {
        out[0] = __ldcg(&g_loss);
        g_loss   = 0.f;        // reset for next graph replay (deterministic)
        g_ticket = 0;
    }
}

extern "C" void kernel_launch(void* const* d_in, const int* in_sizes, int n_in,
                              void* d_out, int out_size)
{
    const int*   pos   = (const int*)d_in[0];
    const int*   neg   = (const int*)d_in[1];
    const int*   rr1   = (const int*)d_in[2];
    const int*   rr2   = (const int*)d_in[3];
    const float* rconf = (const float*)d_in[4];
    const float* ent   = (const float*)d_in[5];
    const float* rel   = (const float*)d_in[6];
    const float* nv    = (const float*)d_in[7];

    int B   = in_sizes[0] / 3;
    int NEG = in_sizes[1] / 3;
    int NR  = in_sizes[2];

    int blocks = (B * 32 + 255) / 256;          // 128 blocks: all wave-1
    all_in_warp<<<blocks, 256>>>(pos, neg, rr1, rr2, rconf, ent, rel, nv,
                                 (float*)d_out, B, NEG, NR);
}

// round 17
// speedup vs baseline: 1.3170x; 1.2973x over previous
#include <cuda_runtime.h>
#include <math.h>

#define DIM 512
#define MARGIN 1.0f
#define RULE_WEIGHT 0.5f

#define MAX_B   1024
#define MAX_NEG 8192

// Scratch (allocation-free rule: __device__ globals)
__device__ float g_dposm[MAX_B];        // MARGIN + d_pos (pre-biased)
__device__ float g_dneg[MAX_NEG];
__device__ float g_rule_sum = 0.f;      // ~40 atomic adds; reset by reduce blk0

__device__ __forceinline__ float warp_red(float v) {
#pragma unroll
    for (int o = 16; o; o >>= 1) v += __shfl_xor_sync(0xffffffffu, v, o);
    return v;
}

// TransH distance via expanded norm — SINGLE streaming pass over w and re,
// nothing but hd[4] + 4 accumulators stays register-resident.
//   u = hd + re
//   ||u - c*w||^2 = uu - 2c*uw + c^2*ww,   c = dw/ww  (dw = hd.w)
__device__ __forceinline__ float dist_lowreg(
    const float4 hd[4],
    const float* __restrict__ rel, const float* __restrict__ nv,
    int r, int lane)
{
    const float4* w4  = reinterpret_cast<const float4*>(nv  + (size_t)r * DIM);
    const float4* re4 = reinterpret_cast<const float4*>(rel + (size_t)r * DIM);
    float ww = 0.f, dw = 0.f, uu = 0.f, uw = 0.f;
#pragma unroll
    for (int i = 0; i < 4; i++) {
        float4 w  = w4[lane + 32 * i];
        float4 re = re4[lane + 32 * i];
        float ux = hd[i].x + re.x, uy = hd[i].y + re.y;
        float uz = hd[i].z + re.z, uq = hd[i].w + re.w;
        ww += w.x * w.x + w.y * w.y + w.z * w.z + w.w * w.w;
        dw += hd[i].x * w.x + hd[i].y * w.y + hd[i].z * w.z + hd[i].w * w.w;
        uu += ux * ux + uy * uy + uz * uz + uq * uq;
        uw += ux * w.x + uy * w.y + uz * w.z + uq * w.w;
    }
    ww = warp_red(ww);
    dw = warp_red(dw);
    uu = warp_red(uu);
    uw = warp_red(uw);
    float c = dw / ww;
    float ss = uu - 2.f * c * uw + c * c * ww;
    return sqrtf(fmaxf(ss, 0.f));
}

// Flat warp-per-task: [0,B) = pos triples (+rule terms), [B,B+NEG) = negs.
// Block 0/tid 0 zeroes out[0] so the reduce node can atomicAdd into it.
__global__ void __launch_bounds__(256)
dist_kernel(const int* __restrict__ pos, const int* __restrict__ neg,
            const int* __restrict__ rr1, const int* __restrict__ rr2,
            const float* __restrict__ rconf,
            const float* __restrict__ ent, const float* __restrict__ rel,
            const float* __restrict__ nv,
            float* __restrict__ out,
            int B, int NEG, int NR)
{
    if (blockIdx.x == 0 && threadIdx.x == 0) out[0] = 0.f;

    int gw   = (blockIdx.x * blockDim.x + threadIdx.x) >> 5;
    int lane = threadIdx.x & 31;
    if (gw >= B + NEG) return;

    int h, r, t;
    bool is_pos = (gw < B);
    if (is_pos) {
        h = pos[3 * gw]; r = pos[3 * gw + 1]; t = pos[3 * gw + 2];
    } else {
        int k = gw - B;
        h = neg[3 * k]; r = neg[3 * k + 1]; t = neg[3 * k + 2];
    }

    const float4* he4 = reinterpret_cast<const float4*>(ent + (size_t)h * DIM);
    const float4* te4 = reinterpret_cast<const float4*>(ent + (size_t)t * DIM);
    float4 hd[4];
#pragma unroll
    for (int i = 0; i < 4; i++) {
        float4 a = he4[lane + 32 * i];
        float4 b = te4[lane + 32 * i];
        hd[i].x = a.x - b.x; hd[i].y = a.y - b.y;
        hd[i].z = a.z - b.z; hd[i].w = a.w - b.w;
    }

    float d = dist_lowreg(hd, rel, nv, r, lane);

    if (is_pos) {
        // Only rules with rule_r1[j] == r contribute (mask exact-zeros the rest).
        float racc = 0.f;
        for (int j = 0; j < NR; j++) {
            if (rr1[j] == r)
                racc += rconf[j] * dist_lowreg(hd, rel, nv, rr2[j], lane);
        }
        if (lane == 0) {
            g_dposm[gw] = MARGIN + d;
            if (racc != 0.f) atomicAdd(&g_rule_sum, racc);   // ~40 warps hit
        }
    } else {
        if (lane == 0) g_dneg[gw - B] = d;
    }
}

// Multi-block one-shot reduce (validated in R9/R11): each thread handles one
// float4 of g_dneg, block-reduces, atomicAdds into out. Block 0 folds the
// rule sum and resets it for the next graph replay.
__global__ void __launch_bounds__(256)
final_reduce(float* __restrict__ out, int B, int NEG)
{
    __shared__ float sb[256];
    int tid  = threadIdx.x;
    int gt   = blockIdx.x * blockDim.x + tid;
    int ratio = NEG / B;
    float inv_neg = 1.0f / (float)NEG;

    float acc = 0.f;
    int nv4 = NEG >> 2;
    if ((ratio & 3) == 0) {
        int vpp = ratio >> 2;   // float4s of g_dneg per pos index
        const float4* n4 = reinterpret_cast<const float4*>(g_dneg);
        for (int q = gt; q < nv4; q += gridDim.x * blockDim.x) {
            float4 v = n4[q];
            float pm = g_dposm[q / vpp];
            float v0 = pm - v.x; acc += (v0 > 0.f) ? v0 : 0.f;
            float v1 = pm - v.y; acc += (v1 > 0.f) ? v1 : 0.f;
            float v2 = pm - v.z; acc += (v2 > 0.f) ? v2 : 0.f;
            float v3 = pm - v.w; acc += (v3 > 0.f) ? v3 : 0.f;
        }
    } else {
        for (int k = gt; k < NEG; k += gridDim.x * blockDim.x) {
            float v = g_dposm[k / ratio] - g_dneg[k];
            acc += (v > 0.f) ? v : 0.f;
        }
    }

    sb[tid] = acc;
    __syncthreads();
    for (int s = 128; s; s >>= 1) {
        if (tid < s) sb[tid] += sb[tid + s];
        __syncthreads();
    }
    if (tid == 0) {
        float contrib = sb[0] * inv_neg;
        if (blockIdx.x == 0) {
            contrib += RULE_WEIGHT * g_rule_sum;
            g_rule_sum = 0.f;          // reset for next replay (deterministic)
        }
        atomicAdd(out, contrib);
    }
}

extern "C" void kernel_launch(void* const* d_in, const int* in_sizes, int n_in,
                              void* d_out, int out_size)
{
    const int*   pos   = (const int*)d_in[0];
    const int*   neg   = (const int*)d_in[1];
    const int*   rr1   = (const int*)d_in[2];
    const int*   rr2   = (const int*)d_in[3];
    const float* rconf = (const float*)d_in[4];
    const float* ent   = (const float*)d_in[5];
    const float* rel   = (const float*)d_in[6];
    const float* nv    = (const float*)d_in[7];

    int B   = in_sizes[0] / 3;
    int NEG = in_sizes[1] / 3;
    int NR  = in_sizes[2];

    int totalWarps = B + NEG;
    int blocks = (totalWarps * 32 + 255) / 256;

    dist_kernel<<<blocks, 256>>>(pos, neg, rr1, rr2, rconf, ent, rel, nv,
                                 (float*)d_out, B, NEG, NR);

    int rthreads = 256;
    int rblocks  = ((NEG >> 2) + rthreads - 1) / rthreads;
    if (rblocks < 1) rblocks = 1;
    final_reduce<<<rblocks, rthreads>>>((float*)d_out, B, NEG);
}